// round 3
// baseline (speedup 1.0000x reference)
#include <cuda_runtime.h>
#include <math.h>

#define BATCH   2
#define LSEQ    2048
#define CDIM    384
#define DI      768
#define DS      16
#define DTR     24
#define MR      (BATCH*LSEQ)     /* 4096 rows */
#define NC      16               /* scan chunks */
#define CH      (LSEQ/NC)        /* 128 steps per chunk */
#define DBC_S   64               /* padded stride for dbc rows (56 used) */

// ---------------- scratch (static device globals; no allocation) ----------
__device__ float g_xn   [MR*CDIM];       // layernorm1 output (B,L,C)
__device__ float g_xz   [MR*2*DI];       // in_proj output (u | z)
__device__ float g_u    [MR*DI];         // conv+silu output
__device__ float g_dbc  [MR*DBC_S];      // x_proj output (dt|B|C), padded
__device__ float g_delta[MR*DI];         // softplus(dt_proj)
__device__ float g_y    [MR*DI];         // scan output after epilogue
__device__ float g_mo   [MR*CDIM];       // out_proj output (mamba out)
__device__ float g_hend [BATCH*NC*DI*DS];
__device__ float g_pend [BATCH*NC*DI*DS];
__device__ float g_hin  [BATCH*NC*DI*DS];

// ---------------- K1: layernorm over C with gather-transpose ---------------
__global__ void k_ln1(const float* __restrict__ x,
                      const float* __restrict__ w,
                      const float* __restrict__ bias) {
    int m = blockIdx.x;               // (b,l)
    int b = m / LSEQ, l = m % LSEQ;
    const float* xp = x + (size_t)b*CDIM*LSEQ + l;
    int tid = threadIdx.x;
    float v[3]; float s = 0.f, s2 = 0.f;
#pragma unroll
    for (int i = 0; i < 3; i++) {
        int c = tid + i*128;
        float t = xp[(size_t)c*LSEQ];
        v[i] = t; s += t; s2 += t*t;
    }
    __shared__ float sh1[128], sh2[128];
    sh1[tid] = s; sh2[tid] = s2; __syncthreads();
    for (int o = 64; o > 0; o >>= 1) {
        if (tid < o) { sh1[tid] += sh1[tid+o]; sh2[tid] += sh2[tid+o]; }
        __syncthreads();
    }
    float mu  = sh1[0] * (1.f/CDIM);
    float var = sh2[0] * (1.f/CDIM) - mu*mu;
    float rs  = rsqrtf(var + 1e-5f);
#pragma unroll
    for (int i = 0; i < 3; i++) {
        int c = tid + i*128;
        g_xn[(size_t)m*CDIM + c] = (v[i]-mu)*rs*w[c] + bias[c];
    }
}

// ---------------- generic SGEMM: C[M,N] = A[M,K] * W[N,K]^T ---------------
// 128x128 tile, 256 threads, 8x8 per thread, K-chunk 8. M%128==0, N%128==0, K%8==0.
__global__ void __launch_bounds__(256)
k_sgemm(const float* __restrict__ A, const float* __restrict__ W,
        float* __restrict__ C, int N, int K) {
    __shared__ float As[8][128];
    __shared__ float Ws[8][128];
    int tid = threadIdx.x;
    int m0 = blockIdx.y * 128, n0 = blockIdx.x * 128;
    int row = tid >> 1, kq = (tid & 1) * 4;
    int ty = tid >> 4, tx = tid & 15;
    float acc[8][8];
#pragma unroll
    for (int i = 0; i < 8; i++)
#pragma unroll
        for (int j = 0; j < 8; j++) acc[i][j] = 0.f;

    const float* Ap = A + (size_t)(m0+row)*K + kq;
    const float* Wp = W + (size_t)(n0+row)*K + kq;

    for (int k0 = 0; k0 < K; k0 += 8) {
        float4 av = *(const float4*)(Ap + k0);
        float4 wv = *(const float4*)(Wp + k0);
        __syncthreads();
        As[kq+0][row] = av.x; As[kq+1][row] = av.y;
        As[kq+2][row] = av.z; As[kq+3][row] = av.w;
        Ws[kq+0][row] = wv.x; Ws[kq+1][row] = wv.y;
        Ws[kq+2][row] = wv.z; Ws[kq+3][row] = wv.w;
        __syncthreads();
#pragma unroll
        for (int kk = 0; kk < 8; kk++) {
            float4 a0 = *(const float4*)&As[kk][ty*8];
            float4 a1 = *(const float4*)&As[kk][ty*8+4];
            float4 w0 = *(const float4*)&Ws[kk][tx*8];
            float4 w1 = *(const float4*)&Ws[kk][tx*8+4];
            float a[8] = {a0.x,a0.y,a0.z,a0.w,a1.x,a1.y,a1.z,a1.w};
            float wr[8] = {w0.x,w0.y,w0.z,w0.w,w1.x,w1.y,w1.z,w1.w};
#pragma unroll
            for (int i = 0; i < 8; i++)
#pragma unroll
                for (int j = 0; j < 8; j++)
                    acc[i][j] = fmaf(a[i], wr[j], acc[i][j]);
        }
    }
#pragma unroll
    for (int i = 0; i < 8; i++) {
        float4 o0 = {acc[i][0], acc[i][1], acc[i][2], acc[i][3]};
        float4 o1 = {acc[i][4], acc[i][5], acc[i][6], acc[i][7]};
        float* cp = C + (size_t)(m0 + ty*8 + i)*N + n0 + tx*8;
        *(float4*)(cp)     = o0;
        *(float4*)(cp + 4) = o1;
    }
}

// ---------------- K3: causal depthwise conv (D_CONV=4) + bias + silu ------
__global__ void k_conv(const float* __restrict__ cw, const float* __restrict__ cb) {
    int idx = blockIdx.x*256 + threadIdx.x;
    int d = idx % DI, m = idx / DI;
    int l = m % LSEQ;
    float acc = cb[d];
#pragma unroll
    for (int j = 0; j < 4; j++) {
        int ll = l - 3 + j;
        if (ll >= 0)
            acc = fmaf(cw[d*4+j], g_xz[(size_t)(m-3+j)*(2*DI) + d], acc);
    }
    float sg = 1.f / (1.f + __expf(-acc));
    g_u[idx] = acc * sg;
}

// ---------------- K4: x_proj  dbc[M,56] = u[M,768] @ xw[56,768]^T ----------
__global__ void __launch_bounds__(256)
k_xproj(const float* __restrict__ W) {
    __shared__ float us[32][68];   // [k][m], padded for fl4 alignment
    __shared__ float ws[56][33];   // [n][k]
    int tid = threadIdx.x;
    int m0 = blockIdx.x * 64;
    int n  = tid & 63, mg = tid >> 6;
    int nn = (n < 56) ? n : 55;
    float acc[16];
#pragma unroll
    for (int i = 0; i < 16; i++) acc[i] = 0.f;

    for (int k0 = 0; k0 < DI; k0 += 32) {
        __syncthreads();
        for (int v = tid; v < 512; v += 256) {
            int mr = v >> 3, kb = v & 7;
            float4 t = *(const float4*)(g_u + (size_t)(m0+mr)*DI + k0 + kb*4);
            us[kb*4+0][mr] = t.x; us[kb*4+1][mr] = t.y;
            us[kb*4+2][mr] = t.z; us[kb*4+3][mr] = t.w;
        }
        for (int v = tid; v < 448; v += 256) {
            int nr = v >> 3, kb = v & 7;
            float4 t = *(const float4*)(W + (size_t)nr*DI + k0 + kb*4);
            ws[nr][kb*4+0] = t.x; ws[nr][kb*4+1] = t.y;
            ws[nr][kb*4+2] = t.z; ws[nr][kb*4+3] = t.w;
        }
        __syncthreads();
#pragma unroll 4
        for (int kk = 0; kk < 32; kk++) {
            float wv = ws[nn][kk];
            float4 u0 = *(const float4*)&us[kk][mg*16+0];
            float4 u1 = *(const float4*)&us[kk][mg*16+4];
            float4 u2 = *(const float4*)&us[kk][mg*16+8];
            float4 u3 = *(const float4*)&us[kk][mg*16+12];
            acc[0]  = fmaf(u0.x, wv, acc[0]);  acc[1]  = fmaf(u0.y, wv, acc[1]);
            acc[2]  = fmaf(u0.z, wv, acc[2]);  acc[3]  = fmaf(u0.w, wv, acc[3]);
            acc[4]  = fmaf(u1.x, wv, acc[4]);  acc[5]  = fmaf(u1.y, wv, acc[5]);
            acc[6]  = fmaf(u1.z, wv, acc[6]);  acc[7]  = fmaf(u1.w, wv, acc[7]);
            acc[8]  = fmaf(u2.x, wv, acc[8]);  acc[9]  = fmaf(u2.y, wv, acc[9]);
            acc[10] = fmaf(u2.z, wv, acc[10]); acc[11] = fmaf(u2.w, wv, acc[11]);
            acc[12] = fmaf(u3.x, wv, acc[12]); acc[13] = fmaf(u3.y, wv, acc[13]);
            acc[14] = fmaf(u3.z, wv, acc[14]); acc[15] = fmaf(u3.w, wv, acc[15]);
        }
    }
    if (n < 56) {
#pragma unroll
        for (int i = 0; i < 16; i++)
            g_dbc[(size_t)(m0 + mg*16 + i)*DBC_S + n] = acc[i];
    }
}

// ---------------- K5: dt_proj + softplus -> delta --------------------------
__global__ void k_dtproj(const float* __restrict__ W, const float* __restrict__ bias) {
    __shared__ float sdt[16][24];
    int tid = threadIdx.x;
    int m0 = blockIdx.x * 16;
    for (int idx = tid; idx < 16*24; idx += 256) {
        int mi = idx / 24, r = idx % 24;
        sdt[mi][r] = g_dbc[(size_t)(m0+mi)*DBC_S + r];
    }
    __syncthreads();
    for (int d = tid; d < DI; d += 256) {
        float wr[24];
#pragma unroll
        for (int r = 0; r < 24; r++) wr[r] = W[d*24 + r];
        float bz = bias[d];
        for (int mi = 0; mi < 16; mi++) {
            float a = bz;
#pragma unroll
            for (int r = 0; r < 24; r++) a = fmaf(sdt[mi][r], wr[r], a);
            float sp = (a > 20.f) ? a : log1pf(expf(a));
            g_delta[(size_t)(m0+mi)*DI + d] = sp;
        }
    }
}

// ---------------- scan helpers ---------------------------------------------
__device__ __forceinline__ void scan_dA(bool fast, float a1, float delta,
                                        const float* __restrict__ Alog, int d,
                                        float dA[DS]) {
    if (fast) {
        float p = __expf(delta * a1);      // dA[s] = p^(s+1)
        dA[0] = p;
#pragma unroll
        for (int s = 1; s < DS; s++) dA[s] = dA[s-1] * p;
    } else {
#pragma unroll
        for (int s = 0; s < DS; s++)
            dA[s] = __expf(delta * (-__expf(Alog[d*DS + s])));
    }
}

// ---------------- K6a: chunk-local scan (carry + product) ------------------
__global__ void __launch_bounds__(256)
k_scan1(const float* __restrict__ Alog) {
    int g = blockIdx.x*256 + threadIdx.x;     // B*NC*DI threads
    int d = g % DI; int rest = g / DI;
    int chunk = rest % NC; int b = rest / NC;

    float a1 = -__expf(Alog[d*DS + 0]);
    bool fast = true;
#pragma unroll
    for (int s = 0; s < DS; s++) {
        float as = -__expf(Alog[d*DS + s]);
        fast = fast && (fabsf(as - (float)(s+1)*a1) <= 1e-4f*fabsf(as) + 1e-12f);
    }
    float h[DS], P[DS];
#pragma unroll
    for (int s = 0; s < DS; s++) { h[s] = 0.f; P[s] = 1.f; }

    int mbase = b*LSEQ + chunk*CH;
    for (int t = 0; t < CH; t++) {
        int m = mbase + t;
        float delta = g_delta[(size_t)m*DI + d];
        float u     = g_u   [(size_t)m*DI + d];
        const float4* bp = (const float4*)(g_dbc + (size_t)m*DBC_S + DTR);
        float4 B0 = bp[0], B1 = bp[1], B2 = bp[2], B3 = bp[3];
        float Bv[DS] = {B0.x,B0.y,B0.z,B0.w, B1.x,B1.y,B1.z,B1.w,
                        B2.x,B2.y,B2.z,B2.w, B3.x,B3.y,B3.z,B3.w};
        float dbu = delta * u;
        float dA[DS];
        scan_dA(fast, a1, delta, Alog, d, dA);
#pragma unroll
        for (int s = 0; s < DS; s++) {
            h[s] = fmaf(dA[s], h[s], dbu * Bv[s]);
            P[s] *= dA[s];
        }
    }
    size_t o = (((size_t)(b*NC + chunk))*DI + d)*DS;
#pragma unroll
    for (int s = 0; s < DS; s++) { g_hend[o+s] = h[s]; g_pend[o+s] = P[s]; }
}

// ---------------- K6b: sequential chunk combine ----------------------------
__global__ void k_comb() {
    int g = blockIdx.x*256 + threadIdx.x;   // B*DI*DS threads
    int s = g % DS; int d = (g/DS) % DI; int b = g/(DS*DI);
    float h = 0.f;
    for (int c = 0; c < NC; c++) {
        size_t o = (((size_t)(b*NC + c))*DI + d)*DS + s;
        g_hin[o] = h;
        h = fmaf(g_pend[o], h, g_hend[o]);
    }
}

// ---------------- K6c: replay with prefix + y + fused epilogue -------------
__global__ void __launch_bounds__(256)
k_scan2(const float* __restrict__ Alog, const float* __restrict__ Dw) {
    int g = blockIdx.x*256 + threadIdx.x;
    int d = g % DI; int rest = g / DI;
    int chunk = rest % NC; int b = rest / NC;

    float a1 = -__expf(Alog[d*DS + 0]);
    bool fast = true;
#pragma unroll
    for (int s = 0; s < DS; s++) {
        float as = -__expf(Alog[d*DS + s]);
        fast = fast && (fabsf(as - (float)(s+1)*a1) <= 1e-4f*fabsf(as) + 1e-12f);
    }
    float Dval = Dw[d];
    float h[DS];
    size_t o = (((size_t)(b*NC + chunk))*DI + d)*DS;
#pragma unroll
    for (int s = 0; s < DS; s++) h[s] = g_hin[o + s];

    int mbase = b*LSEQ + chunk*CH;
    for (int t = 0; t < CH; t++) {
        int m = mbase + t;
        float delta = g_delta[(size_t)m*DI + d];
        float u     = g_u   [(size_t)m*DI + d];
        const float4* bp = (const float4*)(g_dbc + (size_t)m*DBC_S + DTR);
        float4 B0 = bp[0], B1 = bp[1], B2 = bp[2], B3 = bp[3];
        const float4* cp = (const float4*)(g_dbc + (size_t)m*DBC_S + DTR + DS);
        float4 C0 = cp[0], C1 = cp[1], C2 = cp[2], C3 = cp[3];
        float Bv[DS] = {B0.x,B0.y,B0.z,B0.w, B1.x,B1.y,B1.z,B1.w,
                        B2.x,B2.y,B2.z,B2.w, B3.x,B3.y,B3.z,B3.w};
        float Cv[DS] = {C0.x,C0.y,C0.z,C0.w, C1.x,C1.y,C1.z,C1.w,
                        C2.x,C2.y,C2.z,C2.w, C3.x,C3.y,C3.z,C3.w};
        float dbu = delta * u;
        float dA[DS];
        scan_dA(fast, a1, delta, Alog, d, dA);
        float y0 = 0.f, y1 = 0.f, y2 = 0.f, y3 = 0.f;
#pragma unroll
        for (int s = 0; s < 4; s++) {
            h[s]    = fmaf(dA[s],    h[s],    dbu*Bv[s]);    y0 = fmaf(h[s],    Cv[s],    y0);
            h[s+4]  = fmaf(dA[s+4],  h[s+4],  dbu*Bv[s+4]);  y1 = fmaf(h[s+4],  Cv[s+4],  y1);
            h[s+8]  = fmaf(dA[s+8],  h[s+8],  dbu*Bv[s+8]);  y2 = fmaf(h[s+8],  Cv[s+8],  y2);
            h[s+12] = fmaf(dA[s+12], h[s+12], dbu*Bv[s+12]); y3 = fmaf(h[s+12], Cv[s+12], y3);
        }
        float y = (y0 + y1) + (y2 + y3);
        float z = g_xz[(size_t)m*(2*DI) + DI + d];
        float sz = z / (1.f + __expf(-z));
        g_y[(size_t)m*DI + d] = (y + u*Dval) * sz;
    }
}

// ---------------- K9: residual + layernorm2 + scatter-transpose ------------
__global__ void k_ln2(const float* __restrict__ x,
                      const float* __restrict__ w,
                      const float* __restrict__ bias,
                      float* __restrict__ out) {
    int m = blockIdx.x;
    int b = m / LSEQ, l = m % LSEQ;
    const float* xp = x + (size_t)b*CDIM*LSEQ + l;
    int tid = threadIdx.x;
    float v[3]; float s = 0.f, s2 = 0.f;
#pragma unroll
    for (int i = 0; i < 3; i++) {
        int c = tid + i*128;
        float t = xp[(size_t)c*LSEQ] + g_mo[(size_t)m*CDIM + c];
        v[i] = t; s += t; s2 += t*t;
    }
    __shared__ float sh1[128], sh2[128];
    sh1[tid] = s; sh2[tid] = s2; __syncthreads();
    for (int o = 64; o > 0; o >>= 1) {
        if (tid < o) { sh1[tid] += sh1[tid+o]; sh2[tid] += sh2[tid+o]; }
        __syncthreads();
    }
    float mu  = sh1[0] * (1.f/CDIM);
    float var = sh2[0] * (1.f/CDIM) - mu*mu;
    float rs  = rsqrtf(var + 1e-5f);
#pragma unroll
    for (int i = 0; i < 3; i++) {
        int c = tid + i*128;
        out[((size_t)b*CDIM + c)*LSEQ + l] = (v[i]-mu)*rs*w[c] + bias[c];
    }
}

// ---------------- launch ----------------------------------------------------
extern "C" void kernel_launch(void* const* d_in, const int* in_sizes, int n_in,
                              void* d_out, int out_size) {
    const float* x      = (const float*)d_in[0];
    const float* ln1w   = (const float*)d_in[1];
    const float* ln1b   = (const float*)d_in[2];
    const float* ln2w   = (const float*)d_in[3];
    const float* ln2b   = (const float*)d_in[4];
    const float* inpw   = (const float*)d_in[5];   // (1536, 384)
    const float* convw  = (const float*)d_in[6];   // (768, 1, 4)
    const float* convb  = (const float*)d_in[7];
    const float* xprojw = (const float*)d_in[8];   // (56, 768)
    const float* dtw    = (const float*)d_in[9];   // (768, 24)
    const float* dtb    = (const float*)d_in[10];
    const float* alog   = (const float*)d_in[11];  // (768, 16)
    const float* Dd     = (const float*)d_in[12];
    const float* outpw  = (const float*)d_in[13];  // (384, 768)
    float* out = (float*)d_out;

    float *p_xn, *p_xz, *p_y, *p_mo;
    cudaGetSymbolAddress((void**)&p_xn, g_xn);
    cudaGetSymbolAddress((void**)&p_xz, g_xz);
    cudaGetSymbolAddress((void**)&p_y,  g_y);
    cudaGetSymbolAddress((void**)&p_mo, g_mo);

    k_ln1   <<<MR, 128>>>(x, ln1w, ln1b);
    k_sgemm <<<dim3(2*DI/128, MR/128), 256>>>(p_xn, inpw, p_xz, 2*DI, CDIM);
    k_conv  <<<(MR*DI)/256, 256>>>(convw, convb);
    k_xproj <<<MR/64, 256>>>(xprojw);
    k_dtproj<<<MR/16, 256>>>(dtw, dtb);
    k_scan1 <<<(BATCH*NC*DI)/256, 256>>>(alog);
    k_comb  <<<(BATCH*DI*DS)/256, 256>>>();
    k_scan2 <<<(BATCH*NC*DI)/256, 256>>>(alog, Dd);
    k_sgemm <<<dim3(CDIM/128, MR/128), 256>>>(p_y, outpw, p_mo, CDIM, DI);
    k_ln2   <<<MR, 128>>>(x, ln2w, ln2b, out);
}

// round 4
// speedup vs baseline: 1.3819x; 1.3819x over previous
#include <cuda_runtime.h>
#include <math.h>

#define BATCH   2
#define LSEQ    2048
#define CDIM    384
#define DI      768
#define DS      16
#define DTR     24
#define MR      (BATCH*LSEQ)     /* 4096 rows */
#define NC      32               /* scan chunks */
#define CH      (LSEQ/NC)        /* 64 steps per chunk */
#define DBC_S   64               /* padded stride for dbc rows (56 used) */

// ---------------- scratch (static device globals; no allocation) ----------
__device__ float g_xt   [MR*CDIM];       // transposed input (B,L,C)
__device__ float g_xn   [MR*CDIM];       // layernorm1 output (B,L,C)
__device__ float g_xz   [MR*2*DI];       // in_proj output (u | z)
__device__ float g_u    [MR*DI];         // conv+silu output
__device__ float g_dbcp [4*MR*DBC_S];    // x_proj K-split partials
__device__ float g_dbc  [MR*DBC_S];      // x_proj output (dt|B|C), padded
__device__ float g_delta[MR*DI];         // softplus(dt_proj)
__device__ float g_y    [MR*DI];         // scan output after epilogue
__device__ float g_mo   [2*MR*CDIM];     // out_proj K-split partials
__device__ float g_res  [MR*CDIM];       // ln2 output (B,L,C) pre-transpose
__device__ float g_hend [BATCH*NC*DI*DS];
__device__ float g_pend [BATCH*NC*DI*DS];
__device__ float g_hin  [BATCH*NC*DI*DS];

// ---------------- K0: tiled transpose  in[z][R][Cc] -> out[z][Cc][R] ------
__global__ void k_tr(const float* __restrict__ in, float* __restrict__ out,
                     int R, int Cc) {
    __shared__ float t[32][33];
    const float* ip = in  + (size_t)blockIdx.z * R * Cc;
    float*       op = out + (size_t)blockIdx.z * R * Cc;
    int c0 = blockIdx.x * 32;
    int r0 = blockIdx.y * 32;
    int lx = threadIdx.x, ly = threadIdx.y;   // 32 x 8
#pragma unroll
    for (int i = 0; i < 4; i++)
        t[ly + i*8][lx] = ip[(size_t)(r0 + ly + i*8) * Cc + c0 + lx];
    __syncthreads();
#pragma unroll
    for (int i = 0; i < 4; i++)
        op[(size_t)(c0 + ly + i*8) * R + r0 + lx] = t[lx][ly + i*8];
}

// ---------------- K1: layernorm over C (row-major, coalesced) --------------
__global__ void k_ln1(const float* __restrict__ xt,
                      const float* __restrict__ w,
                      const float* __restrict__ bias) {
    int m = blockIdx.x;
    int tid = threadIdx.x;
    const float* xp = xt + (size_t)m * CDIM;
    float v[3]; float s = 0.f, s2 = 0.f;
#pragma unroll
    for (int i = 0; i < 3; i++) {
        int c = tid + i*128;
        float t = xp[c];
        v[i] = t; s += t; s2 += t*t;
    }
    __shared__ float sh1[128], sh2[128];
    sh1[tid] = s; sh2[tid] = s2; __syncthreads();
    for (int o = 64; o > 0; o >>= 1) {
        if (tid < o) { sh1[tid] += sh1[tid+o]; sh2[tid] += sh2[tid+o]; }
        __syncthreads();
    }
    float mu  = sh1[0] * (1.f/CDIM);
    float var = sh2[0] * (1.f/CDIM) - mu*mu;
    float rs  = rsqrtf(var + 1e-5f);
#pragma unroll
    for (int i = 0; i < 3; i++) {
        int c = tid + i*128;
        g_xn[(size_t)m*CDIM + c] = (v[i]-mu)*rs*w[c] + bias[c];
    }
}

// ---------------- SGEMM: C[M,N] += A[M,K]*W[N,K]^T (z = K-split slice) ----
// 128x128 tile, 256 threads, 8x8 per thread, K-chunk 8.
__global__ void __launch_bounds__(256, 2)
k_sgemm(const float* __restrict__ A, const float* __restrict__ W,
        float* __restrict__ C, int N, int K, int lda, int ldw, int csstride) {
    __shared__ float As[8][128];
    __shared__ float Ws[8][128];
    int tid = threadIdx.x;
    int m0 = blockIdx.y * 128, n0 = blockIdx.x * 128;
    int z = blockIdx.z;
    A += (size_t)z * K;                 // K-split offset along row
    W += (size_t)z * K;
    C += (size_t)z * csstride;
    int row = tid >> 1, kq = (tid & 1) * 4;
    int ty = tid >> 4, tx = tid & 15;
    float acc[8][8];
#pragma unroll
    for (int i = 0; i < 8; i++)
#pragma unroll
        for (int j = 0; j < 8; j++) acc[i][j] = 0.f;

    const float* Ap = A + (size_t)(m0+row)*lda + kq;
    const float* Wp = W + (size_t)(n0+row)*ldw + kq;

    for (int k0 = 0; k0 < K; k0 += 8) {
        float4 av = *(const float4*)(Ap + k0);
        float4 wv = *(const float4*)(Wp + k0);
        __syncthreads();
        As[kq+0][row] = av.x; As[kq+1][row] = av.y;
        As[kq+2][row] = av.z; As[kq+3][row] = av.w;
        Ws[kq+0][row] = wv.x; Ws[kq+1][row] = wv.y;
        Ws[kq+2][row] = wv.z; Ws[kq+3][row] = wv.w;
        __syncthreads();
#pragma unroll
        for (int kk = 0; kk < 8; kk++) {
            float4 a0 = *(const float4*)&As[kk][ty*8];
            float4 a1 = *(const float4*)&As[kk][ty*8+4];
            float4 w0 = *(const float4*)&Ws[kk][tx*8];
            float4 w1 = *(const float4*)&Ws[kk][tx*8+4];
            float a[8] = {a0.x,a0.y,a0.z,a0.w,a1.x,a1.y,a1.z,a1.w};
            float wr[8] = {w0.x,w0.y,w0.z,w0.w,w1.x,w1.y,w1.z,w1.w};
#pragma unroll
            for (int i = 0; i < 8; i++)
#pragma unroll
                for (int j = 0; j < 8; j++)
                    acc[i][j] = fmaf(a[i], wr[j], acc[i][j]);
        }
    }
#pragma unroll
    for (int i = 0; i < 8; i++) {
        float4 o0 = {acc[i][0], acc[i][1], acc[i][2], acc[i][3]};
        float4 o1 = {acc[i][4], acc[i][5], acc[i][6], acc[i][7]};
        float* cp = C + (size_t)(m0 + ty*8 + i)*N + n0 + tx*8;
        *(float4*)(cp)     = o0;
        *(float4*)(cp + 4) = o1;
    }
}

// ---------------- K3: causal depthwise conv (D_CONV=4) + bias + silu ------
__global__ void k_conv(const float* __restrict__ cw, const float* __restrict__ cb) {
    int idx = blockIdx.x*256 + threadIdx.x;
    int d = idx % DI, m = idx / DI;
    int l = m % LSEQ;
    float acc = cb[d];
#pragma unroll
    for (int j = 0; j < 4; j++) {
        int ll = l - 3 + j;
        if (ll >= 0)
            acc = fmaf(cw[d*4+j], g_xz[(size_t)(m-3+j)*(2*DI) + d], acc);
    }
    float sg = 1.f / (1.f + __expf(-acc));
    g_u[idx] = acc * sg;
}

// ---------------- K4: x_proj partial  (K-split via blockIdx.y) -------------
// dbc_part[z][M,56] = u[M, z*192:(z+1)*192] @ xw[56, same]^T
__global__ void __launch_bounds__(256)
k_xproj(const float* __restrict__ W) {
    __shared__ float us[32][68];   // [k][m]
    __shared__ float ws[56][33];   // [n][k]
    int tid = threadIdx.x;
    int m0 = blockIdx.x * 64;
    int z  = blockIdx.y;
    int kbase = z * (DI/4);        // 192
    int n  = tid & 63, mg = tid >> 6;
    int nn = (n < 56) ? n : 55;
    float acc[16];
#pragma unroll
    for (int i = 0; i < 16; i++) acc[i] = 0.f;

    for (int k0 = kbase; k0 < kbase + DI/4; k0 += 32) {
        __syncthreads();
        for (int v = tid; v < 512; v += 256) {
            int mr = v >> 3, kb = v & 7;
            float4 t = *(const float4*)(g_u + (size_t)(m0+mr)*DI + k0 + kb*4);
            us[kb*4+0][mr] = t.x; us[kb*4+1][mr] = t.y;
            us[kb*4+2][mr] = t.z; us[kb*4+3][mr] = t.w;
        }
        for (int v = tid; v < 448; v += 256) {
            int nr = v >> 3, kb = v & 7;
            float4 t = *(const float4*)(W + (size_t)nr*DI + k0 + kb*4);
            ws[nr][kb*4+0] = t.x; ws[nr][kb*4+1] = t.y;
            ws[nr][kb*4+2] = t.z; ws[nr][kb*4+3] = t.w;
        }
        __syncthreads();
#pragma unroll 4
        for (int kk = 0; kk < 32; kk++) {
            float wv = ws[nn][kk];
            float4 u0 = *(const float4*)&us[kk][mg*16+0];
            float4 u1 = *(const float4*)&us[kk][mg*16+4];
            float4 u2 = *(const float4*)&us[kk][mg*16+8];
            float4 u3 = *(const float4*)&us[kk][mg*16+12];
            acc[0]  = fmaf(u0.x, wv, acc[0]);  acc[1]  = fmaf(u0.y, wv, acc[1]);
            acc[2]  = fmaf(u0.z, wv, acc[2]);  acc[3]  = fmaf(u0.w, wv, acc[3]);
            acc[4]  = fmaf(u1.x, wv, acc[4]);  acc[5]  = fmaf(u1.y, wv, acc[5]);
            acc[6]  = fmaf(u1.z, wv, acc[6]);  acc[7]  = fmaf(u1.w, wv, acc[7]);
            acc[8]  = fmaf(u2.x, wv, acc[8]);  acc[9]  = fmaf(u2.y, wv, acc[9]);
            acc[10] = fmaf(u2.z, wv, acc[10]); acc[11] = fmaf(u2.w, wv, acc[11]);
            acc[12] = fmaf(u3.x, wv, acc[12]); acc[13] = fmaf(u3.y, wv, acc[13]);
            acc[14] = fmaf(u3.z, wv, acc[14]); acc[15] = fmaf(u3.w, wv, acc[15]);
        }
    }
    if (n < 56) {
#pragma unroll
        for (int i = 0; i < 16; i++)
            g_dbcp[((size_t)z*MR + m0 + mg*16 + i)*DBC_S + n] = acc[i];
    }
}

// ---------------- K4b: reduce the 4 K-split partials -----------------------
__global__ void k_dbcred() {
    size_t i = (size_t)blockIdx.x*256 + threadIdx.x;    // < MR*DBC_S
    g_dbc[i] = (g_dbcp[i] + g_dbcp[(size_t)MR*DBC_S + i])
             + (g_dbcp[2*(size_t)MR*DBC_S + i] + g_dbcp[3*(size_t)MR*DBC_S + i]);
}

// ---------------- K5: dt_proj + softplus -> delta --------------------------
__global__ void k_dtproj(const float* __restrict__ W, const float* __restrict__ bias) {
    __shared__ float sdt[16][24];
    int tid = threadIdx.x;
    int m0 = blockIdx.x * 16;
    for (int idx = tid; idx < 16*24; idx += 256) {
        int mi = idx / 24, r = idx % 24;
        sdt[mi][r] = g_dbc[(size_t)(m0+mi)*DBC_S + r];
    }
    __syncthreads();
    for (int d = tid; d < DI; d += 256) {
        float wr[24];
#pragma unroll
        for (int r = 0; r < 24; r++) wr[r] = W[d*24 + r];
        float bz = bias[d];
        for (int mi = 0; mi < 16; mi++) {
            float a = bz;
#pragma unroll
            for (int r = 0; r < 24; r++) a = fmaf(sdt[mi][r], wr[r], a);
            float sp = (a > 20.f) ? a : log1pf(expf(a));
            g_delta[(size_t)(m0+mi)*DI + d] = sp;
        }
    }
}

// ---------------- scan helpers ---------------------------------------------
__device__ __forceinline__ void scan_dA(bool fast, float a1, float delta,
                                        const float* __restrict__ Alog, int d,
                                        float dA[DS]) {
    if (fast) {
        float p = __expf(delta * a1);      // dA[s] = p^(s+1)
        dA[0] = p;
#pragma unroll
        for (int s = 1; s < DS; s++) dA[s] = dA[s-1] * p;
    } else {
#pragma unroll
        for (int s = 0; s < DS; s++)
            dA[s] = __expf(delta * (-__expf(Alog[d*DS + s])));
    }
}

__device__ __forceinline__ bool fast_check(const float* __restrict__ Alog,
                                           int d, float& a1) {
    a1 = -__expf(Alog[d*DS + 0]);
    bool fast = true;
#pragma unroll
    for (int s = 0; s < DS; s++) {
        float as = -__expf(Alog[d*DS + s]);
        fast = fast && (fabsf(as - (float)(s+1)*a1) <= 1e-4f*fabsf(as) + 1e-12f);
    }
    return fast;
}

// ---------------- K6a: chunk-local scan (carry + product) ------------------
__global__ void __launch_bounds__(256)
k_scan1(const float* __restrict__ Alog) {
    int g = blockIdx.x*256 + threadIdx.x;     // B*NC*DI threads
    int d = g % DI; int rest = g / DI;
    int chunk = rest % NC; int b = rest / NC;

    float a1; bool fast = fast_check(Alog, d, a1);
    float h[DS], P[DS];
#pragma unroll
    for (int s = 0; s < DS; s++) { h[s] = 0.f; P[s] = 1.f; }

    int mbase = b*LSEQ + chunk*CH;
    for (int t = 0; t < CH; t++) {
        int m = mbase + t;
        float delta = g_delta[(size_t)m*DI + d];
        float u     = g_u   [(size_t)m*DI + d];
        const float4* bp = (const float4*)(g_dbc + (size_t)m*DBC_S + DTR);
        float4 B0 = bp[0], B1 = bp[1], B2 = bp[2], B3 = bp[3];
        float Bv[DS] = {B0.x,B0.y,B0.z,B0.w, B1.x,B1.y,B1.z,B1.w,
                        B2.x,B2.y,B2.z,B2.w, B3.x,B3.y,B3.z,B3.w};
        float dbu = delta * u;
        float dA[DS];
        scan_dA(fast, a1, delta, Alog, d, dA);
#pragma unroll
        for (int s = 0; s < DS; s++) {
            h[s] = fmaf(dA[s], h[s], dbu * Bv[s]);
            P[s] *= dA[s];
        }
    }
    size_t o = (((size_t)(b*NC + chunk))*DI + d)*DS;
#pragma unroll
    for (int s = 0; s < DS; s++) { g_hend[o+s] = h[s]; g_pend[o+s] = P[s]; }
}

// ---------------- K6b: sequential chunk combine ----------------------------
__global__ void k_comb() {
    int g = blockIdx.x*256 + threadIdx.x;   // B*DI*DS threads
    int s = g % DS; int d = (g/DS) % DI; int b = g/(DS*DI);
    float h = 0.f;
    for (int c = 0; c < NC; c++) {
        size_t o = (((size_t)(b*NC + c))*DI + d)*DS + s;
        g_hin[o] = h;
        h = fmaf(g_pend[o], h, g_hend[o]);
    }
}

// ---------------- K6c: replay with prefix + y + fused epilogue -------------
__global__ void __launch_bounds__(256)
k_scan2(const float* __restrict__ Alog, const float* __restrict__ Dw) {
    int g = blockIdx.x*256 + threadIdx.x;
    int d = g % DI; int rest = g / DI;
    int chunk = rest % NC; int b = rest / NC;

    float a1; bool fast = fast_check(Alog, d, a1);
    float Dval = Dw[d];
    float h[DS];
    size_t o = (((size_t)(b*NC + chunk))*DI + d)*DS;
#pragma unroll
    for (int s = 0; s < DS; s++) h[s] = g_hin[o + s];

    int mbase = b*LSEQ + chunk*CH;
    for (int t = 0; t < CH; t++) {
        int m = mbase + t;
        float delta = g_delta[(size_t)m*DI + d];
        float u     = g_u   [(size_t)m*DI + d];
        const float4* bp = (const float4*)(g_dbc + (size_t)m*DBC_S + DTR);
        float4 B0 = bp[0], B1 = bp[1], B2 = bp[2], B3 = bp[3];
        const float4* cp = (const float4*)(g_dbc + (size_t)m*DBC_S + DTR + DS);
        float4 C0 = cp[0], C1 = cp[1], C2 = cp[2], C3 = cp[3];
        float Bv[DS] = {B0.x,B0.y,B0.z,B0.w, B1.x,B1.y,B1.z,B1.w,
                        B2.x,B2.y,B2.z,B2.w, B3.x,B3.y,B3.z,B3.w};
        float Cv[DS] = {C0.x,C0.y,C0.z,C0.w, C1.x,C1.y,C1.z,C1.w,
                        C2.x,C2.y,C2.z,C2.w, C3.x,C3.y,C3.z,C3.w};
        float dbu = delta * u;
        float dA[DS];
        scan_dA(fast, a1, delta, Alog, d, dA);
        float y0 = 0.f, y1 = 0.f, y2 = 0.f, y3 = 0.f;
#pragma unroll
        for (int s = 0; s < 4; s++) {
            h[s]    = fmaf(dA[s],    h[s],    dbu*Bv[s]);    y0 = fmaf(h[s],    Cv[s],    y0);
            h[s+4]  = fmaf(dA[s+4],  h[s+4],  dbu*Bv[s+4]);  y1 = fmaf(h[s+4],  Cv[s+4],  y1);
            h[s+8]  = fmaf(dA[s+8],  h[s+8],  dbu*Bv[s+8]);  y2 = fmaf(h[s+8],  Cv[s+8],  y2);
            h[s+12] = fmaf(dA[s+12], h[s+12], dbu*Bv[s+12]); y3 = fmaf(h[s+12], Cv[s+12], y3);
        }
        float y = (y0 + y1) + (y2 + y3);
        float z = g_xz[(size_t)m*(2*DI) + DI + d];
        float sz = z / (1.f + __expf(-z));
        g_y[(size_t)m*DI + d] = (y + u*Dval) * sz;
    }
}

// ---------------- K9: residual + layernorm2 (row-major, coalesced) ---------
__global__ void k_ln2(const float* __restrict__ xt,
                      const float* __restrict__ w,
                      const float* __restrict__ bias) {
    int m = blockIdx.x;
    int tid = threadIdx.x;
    const float* xp = xt + (size_t)m * CDIM;
    float v[3]; float s = 0.f, s2 = 0.f;
#pragma unroll
    for (int i = 0; i < 3; i++) {
        int c = tid + i*128;
        float t = xp[c] + g_mo[(size_t)m*CDIM + c]
                        + g_mo[(size_t)MR*CDIM + (size_t)m*CDIM + c];
        v[i] = t; s += t; s2 += t*t;
    }
    __shared__ float sh1[128], sh2[128];
    sh1[tid] = s; sh2[tid] = s2; __syncthreads();
    for (int o = 64; o > 0; o >>= 1) {
        if (tid < o) { sh1[tid] += sh1[tid+o]; sh2[tid] += sh2[tid+o]; }
        __syncthreads();
    }
    float mu  = sh1[0] * (1.f/CDIM);
    float var = sh2[0] * (1.f/CDIM) - mu*mu;
    float rs  = rsqrtf(var + 1e-5f);
#pragma unroll
    for (int i = 0; i < 3; i++) {
        int c = tid + i*128;
        g_res[(size_t)m*CDIM + c] = (v[i]-mu)*rs*w[c] + bias[c];
    }
}

// ---------------- launch ----------------------------------------------------
extern "C" void kernel_launch(void* const* d_in, const int* in_sizes, int n_in,
                              void* d_out, int out_size) {
    const float* x      = (const float*)d_in[0];
    const float* ln1w   = (const float*)d_in[1];
    const float* ln1b   = (const float*)d_in[2];
    const float* ln2w   = (const float*)d_in[3];
    const float* ln2b   = (const float*)d_in[4];
    const float* inpw   = (const float*)d_in[5];   // (1536, 384)
    const float* convw  = (const float*)d_in[6];   // (768, 1, 4)
    const float* convb  = (const float*)d_in[7];
    const float* xprojw = (const float*)d_in[8];   // (56, 768)
    const float* dtw    = (const float*)d_in[9];   // (768, 24)
    const float* dtb    = (const float*)d_in[10];
    const float* alog   = (const float*)d_in[11];  // (768, 16)
    const float* Dd     = (const float*)d_in[12];
    const float* outpw  = (const float*)d_in[13];  // (384, 768)
    float* out = (float*)d_out;

    float *p_xt, *p_xn, *p_xz, *p_y, *p_mo, *p_res;
    cudaGetSymbolAddress((void**)&p_xt,  g_xt);
    cudaGetSymbolAddress((void**)&p_xn,  g_xn);
    cudaGetSymbolAddress((void**)&p_xz,  g_xz);
    cudaGetSymbolAddress((void**)&p_y,   g_y);
    cudaGetSymbolAddress((void**)&p_mo,  g_mo);
    cudaGetSymbolAddress((void**)&p_res, g_res);

    // x (B,C,L) -> g_xt (B,L,C)
    k_tr    <<<dim3(LSEQ/32, CDIM/32, BATCH), dim3(32,8)>>>(x, p_xt, CDIM, LSEQ);
    k_ln1   <<<MR, 128>>>(p_xt, ln1w, ln1b);
    k_sgemm <<<dim3(2*DI/128, MR/128, 1), 256>>>(p_xn, inpw, p_xz,
                                                 2*DI, CDIM, CDIM, CDIM, 0);
    k_conv  <<<(MR*DI)/256, 256>>>(convw, convb);
    k_xproj <<<dim3(MR/64, 4), 256>>>(xprojw);
    k_dbcred<<<(MR*DBC_S)/256, 256>>>();
    k_dtproj<<<MR/16, 256>>>(dtw, dtb);
    k_scan1 <<<(BATCH*NC*DI)/256, 256>>>(alog);
    k_comb  <<<(BATCH*DI*DS)/256, 256>>>();
    k_scan2 <<<(BATCH*NC*DI)/256, 256>>>(alog, Dd);
    // out_proj with K-split 2: two partial products, summed inside ln2
    k_sgemm <<<dim3(CDIM/128, MR/128, 2), 256>>>(p_y, outpw, p_mo,
                                                 CDIM, DI/2, DI, DI, MR*CDIM);
    k_ln2   <<<MR, 128>>>(p_xt, ln2w, ln2b);
    // g_res (B,L,C) -> out (B,C,L)
    k_tr    <<<dim3(CDIM/32, LSEQ/32, BATCH), dim3(32,8)>>>(p_res, out, LSEQ, CDIM);
}